// round 4
// baseline (speedup 1.0000x reference)
#include <cuda_runtime.h>

#define BQ    32      // queries per batch
#define BD    512     // docs per batch
#define EDIM  300     // embedding dim
#define NK    11      // RBF kernels
#define DCH   128     // doc rows per SMEM chunk
#define RS    308     // row stride in floats (77 granules, odd -> conflict-free)
#define NTH   256
#define NCHUNK (BD / DCH)

typedef unsigned long long ull;

__device__ __constant__ float c_mu[NK] =
    {1.0f, 0.9f, 0.7f, 0.5f, 0.3f, 0.1f, -0.1f, -0.3f, -0.5f, -0.7f, -0.9f};
// log2e * (-1/(2 sigma^2)):  sigma0=1e-4 -> -5e7*log2e ; sigma=0.1 -> -50*log2e
__device__ __constant__ float c_cl[NK] =
    {-7.2134752e7f, -72.134752f, -72.134752f, -72.134752f, -72.134752f, -72.134752f,
     -72.134752f, -72.134752f, -72.134752f, -72.134752f, -72.134752f};

__device__ __forceinline__ float warp_sum(float v) {
    v += __shfl_xor_sync(0xffffffffu, v, 16);
    v += __shfl_xor_sync(0xffffffffu, v, 8);
    v += __shfl_xor_sync(0xffffffffu, v, 4);
    v += __shfl_xor_sync(0xffffffffu, v, 2);
    v += __shfl_xor_sync(0xffffffffu, v, 1);
    return v;
}

__device__ __forceinline__ unsigned sm_u32(const void* p) {
    unsigned r;
    asm("{ .reg .u64 t; cvta.to.shared.u64 t, %1; cvt.u32.u64 %0, t; }"
        : "=r"(r) : "l"(p));
    return r;
}

__device__ __forceinline__ void lds_v2u64(ull& lo, ull& hi, unsigned addr) {
    asm volatile("ld.shared.v2.u64 {%0, %1}, [%2];"
                 : "=l"(lo), "=l"(hi) : "r"(addr));
}

__device__ __forceinline__ void fma2(ull& acc, ull a, ull b) {
    asm("fma.rn.f32x2 %0, %1, %2, %0;" : "+l"(acc) : "l"(a), "l"(b));
}

__device__ __forceinline__ float ex2(float x) {
    float r;
    asm("ex2.approx.f32 %0, %1;" : "=f"(r) : "f"(x));
    return r;
}

// Load one embedding row (300 floats) into smem row-major, coalesced.
// Returns partial sum of squares (caller warp-reduces).
__device__ __forceinline__ float load_row(const float* __restrict__ emb, int tok,
                                          float* dst, int lane) {
    const float4* src = reinterpret_cast<const float4*>(emb) + (size_t)tok * (EDIM / 4);
    float4* d4 = reinterpret_cast<float4*>(dst);
    float ssq = 0.0f;
    float4 v;
    v = src[lane];
    ssq += v.x*v.x + v.y*v.y + v.z*v.z + v.w*v.w;
    d4[lane] = v;
    v = src[lane + 32];
    ssq += v.x*v.x + v.y*v.y + v.z*v.z + v.w*v.w;
    d4[lane + 32] = v;
    if (lane < 11) {   // 75 float4 per row = 32 + 32 + 11
        v = src[lane + 64];
        ssq += v.x*v.x + v.y*v.y + v.z*v.z + v.w*v.w;
        d4[lane + 64] = v;
    }
    return ssq;
}

__global__ __launch_bounds__(NTH, 1)
void knrm_kernel(const int* __restrict__ qt,
                 const int* __restrict__ dt,
                 const float* __restrict__ emb,
                 const float* __restrict__ fcw,
                 const float* __restrict__ fcb,
                 float* __restrict__ out)
{
    extern __shared__ float sm[];
    float* dR = sm;                      // [DCH][RS] row-major doc tile
    float* qR = dR + DCH * RS;           // [BQ][RS]  row-major query tile
    float* rq = qR + BQ * RS;            // [BQ]
    float* wq = rq + BQ;                 // [BQ]
    float* rd = wq + BQ;                 // [DCH]
    float* wd = rd + DCH;                // [DCH]
    float* qk = wd + DCH;                // [BQ][NK]

    const int b    = blockIdx.x;
    const int tid  = threadIdx.x;
    const int lane = tid & 31;
    const int warp = tid >> 5;

    for (int i = tid; i < BQ * NK; i += NTH) qk[i] = 0.0f;

    // ---- load 32 query rows (4 per warp) ----
    #pragma unroll
    for (int r = 0; r < BQ / 8; ++r) {
        const int q   = warp * (BQ / 8) + r;
        const int tok = qt[b * BQ + q];
        float ssq = warp_sum(load_row(emb, tok, qR + q * RS, lane));
        if (lane == 0) {
            rq[q] = 1.0f / (sqrtf(ssq) + 1e-13f);
            wq[q] = (tok > 0) ? 1.0f : 0.0f;
        }
    }

    // compute mapping: tq in [0,8) -> q rows {tq, tq+8, tq+16, tq+24}
    //                  tdg in [0,32) -> d rows {tdg, tdg+32, tdg+64, tdg+96}
    const int tq  = tid & 7;
    const int tdg = tid >> 3;
    const unsigned qA = sm_u32(qR) + (unsigned)tq  * (RS * 4);
    const unsigned dA = sm_u32(dR) + (unsigned)tdg * (RS * 4);

    float acc[4][NK];
    #pragma unroll
    for (int i = 0; i < 4; ++i)
        #pragma unroll
        for (int k = 0; k < NK; ++k) acc[i][k] = 0.0f;

    float rqv[4], wqv[4];

    for (int ch = 0; ch < NCHUNK; ++ch) {
        __syncthreads();   // previous chunk readers done

        // ---- load 128 doc rows (16 per warp) ----
        #pragma unroll 2
        for (int r = 0; r < DCH / 8; ++r) {
            const int dloc = warp * (DCH / 8) + r;
            const int tok  = dt[b * BD + ch * DCH + dloc];
            float ssq = warp_sum(load_row(emb, tok, dR + dloc * RS, lane));
            if (lane == 0) {
                rd[dloc] = 1.0f / (sqrtf(ssq) + 1e-13f);
                wd[dloc] = (tok > 0) ? 1.0f : 0.0f;
            }
        }
        __syncthreads();

        if (ch == 0) {
            #pragma unroll
            for (int i = 0; i < 4; ++i) {
                rqv[i] = rq[tq + 8 * i];
                wqv[i] = wq[tq + 8 * i];
            }
        }

        // ---- 4x4 GEMM over E=300 with packed f32x2 (lo=even e, hi=odd e) ----
        ull acc2[4][4];
        #pragma unroll
        for (int i = 0; i < 4; ++i)
            #pragma unroll
            for (int j = 0; j < 4; ++j) acc2[i][j] = 0ull;

        unsigned qa = qA, da = dA;
        #pragma unroll 3
        for (int it = 0; it < EDIM / 4; ++it) {
            ull ql[4][2], dl[4][2];
            #pragma unroll
            for (int i = 0; i < 4; ++i)
                lds_v2u64(ql[i][0], ql[i][1], qa + i * (8 * RS * 4));
            #pragma unroll
            for (int j = 0; j < 4; ++j)
                lds_v2u64(dl[j][0], dl[j][1], da + j * (32 * RS * 4));
            #pragma unroll
            for (int i = 0; i < 4; ++i)
                #pragma unroll
                for (int j = 0; j < 4; ++j) {
                    fma2(acc2[i][j], ql[i][0], dl[j][0]);
                    fma2(acc2[i][j], ql[i][1], dl[j][1]);
                }
            qa += 16; da += 16;
        }

        // ---- RBF epilogue ----
        float rdv[4], wdv[4];
        #pragma unroll
        for (int j = 0; j < 4; ++j) {
            rdv[j] = rd[tdg + 32 * j];
            wdv[j] = wd[tdg + 32 * j];
        }
        #pragma unroll
        for (int i = 0; i < 4; ++i) {
            #pragma unroll
            for (int j = 0; j < 4; ++j) {
                float lo, hi;
                asm("mov.b64 {%0, %1}, %2;" : "=f"(lo), "=f"(hi) : "l"(acc2[i][j]));
                const float m = (lo + hi) * (rqv[i] * rdv[j]);
                const float w = wqv[i] * wdv[j];
                #pragma unroll
                for (int k = 0; k < NK; ++k) {
                    const float d0 = m - c_mu[k];
                    acc[i][k] = fmaf(w, ex2(d0 * d0 * c_cl[k]), acc[i][k]);
                }
            }
        }
    }

    // ---- reduce over d-groups: 4-way shfl + 8-warp shared atomics ----
    #pragma unroll
    for (int i = 0; i < 4; ++i) {
        #pragma unroll
        for (int k = 0; k < NK; ++k) {
            float v = acc[i][k];
            v += __shfl_down_sync(0xffffffffu, v, 16);
            v += __shfl_down_sync(0xffffffffu, v, 8);
            if (lane < 8) atomicAdd(&qk[(tq + 8 * i) * NK + k], v);
        }
    }
    __syncthreads();

    // ---- log-pool over Q, FC, write score ----
    if (tid < BQ) {
        float s = 0.0f;
        #pragma unroll
        for (int k = 0; k < NK; ++k)
            s += fcw[k] * 0.01f * logf(fmaxf(qk[tid * NK + k], 1e-10f));
        s = warp_sum(s);
        if (lane == 0) out[b] = s + fcb[0];
    }
}

extern "C" void kernel_launch(void* const* d_in, const int* in_sizes, int n_in,
                              void* d_out, int out_size)
{
    const int*   qt  = (const int*)d_in[0];
    const int*   dt  = (const int*)d_in[1];
    const float* emb = (const float*)d_in[2];
    const float* fcw = (const float*)d_in[3];
    const float* fcb = (const float*)d_in[4];
    float* out = (float*)d_out;

    const int B = in_sizes[0] / BQ;   // 256

    const size_t smem = (size_t)(DCH * RS + BQ * RS + 2 * BQ + 2 * DCH + BQ * NK)
                        * sizeof(float);   // ~199.8 KB
    cudaFuncSetAttribute(knrm_kernel,
                         cudaFuncAttributeMaxDynamicSharedMemorySize, (int)smem);
    knrm_kernel<<<B, NTH, smem>>>(qt, dt, emb, fcw, fcb, out);
}

// round 7
// speedup vs baseline: 1.6657x; 1.6657x over previous
#include <cuda_runtime.h>

#define BQ    32      // queries per batch
#define BD    512     // docs per batch
#define EDIM  300     // embedding dim
#define NK    11      // RBF kernels
#define DCH   128     // doc rows per SMEM chunk
#define RS    300     // row stride floats = 75 granules (odd -> conflict-free)
#define NTH   512
#define NCHUNK (BD / DCH)
#define IT_COMMON 37  // granule-iters both E-halves do; eh0 does 1 extra (38+37=75)

typedef unsigned long long ull;

__device__ __constant__ float c_mu[NK] =
    {1.0f, 0.9f, 0.7f, 0.5f, 0.3f, 0.1f, -0.1f, -0.3f, -0.5f, -0.7f, -0.9f};
// log2e * (-1/(2 sigma^2)):  sigma0=1e-4 ; sigma=0.1
__device__ __constant__ float c_cl[NK] =
    {-7.2134752e7f, -72.134752f, -72.134752f, -72.134752f, -72.134752f, -72.134752f,
     -72.134752f, -72.134752f, -72.134752f, -72.134752f, -72.134752f};

__device__ __forceinline__ float warp_sum(float v) {
    v += __shfl_xor_sync(0xffffffffu, v, 16);
    v += __shfl_xor_sync(0xffffffffu, v, 8);
    v += __shfl_xor_sync(0xffffffffu, v, 4);
    v += __shfl_xor_sync(0xffffffffu, v, 2);
    v += __shfl_xor_sync(0xffffffffu, v, 1);
    return v;
}

__device__ __forceinline__ unsigned sm_u32(const void* p) {
    unsigned r;
    asm("{ .reg .u64 t; cvta.to.shared.u64 t, %1; cvt.u32.u64 %0, t; }"
        : "=r"(r) : "l"(p));
    return r;
}

__device__ __forceinline__ void lds_v2u64(ull& lo, ull& hi, unsigned addr) {
    asm volatile("ld.shared.v2.u64 {%0, %1}, [%2];"
                 : "=l"(lo), "=l"(hi) : "r"(addr));
}

__device__ __forceinline__ void fma2(ull& acc, ull a, ull b) {
    asm("fma.rn.f32x2 %0, %1, %2, %0;" : "+l"(acc) : "l"(a), "l"(b));
}

__device__ __forceinline__ float ex2(float x) {
    float r;
    asm("ex2.approx.f32 %0, %1;" : "=f"(r) : "f"(x));
    return r;
}

// Load one embedding row (300 floats) into smem row-major, coalesced.
__device__ __forceinline__ float load_row(const float* __restrict__ emb, int tok,
                                          float* dst, int lane) {
    const float4* src = reinterpret_cast<const float4*>(emb) + (size_t)tok * (EDIM / 4);
    float4* d4 = reinterpret_cast<float4*>(dst);
    float ssq = 0.0f;
    float4 v;
    v = src[lane];
    ssq += v.x*v.x + v.y*v.y + v.z*v.z + v.w*v.w;
    d4[lane] = v;
    v = src[lane + 32];
    ssq += v.x*v.x + v.y*v.y + v.z*v.z + v.w*v.w;
    d4[lane + 32] = v;
    if (lane < 11) {   // 75 float4 per row = 32 + 32 + 11
        v = src[lane + 64];
        ssq += v.x*v.x + v.y*v.y + v.z*v.z + v.w*v.w;
        d4[lane + 64] = v;
    }
    return ssq;
}

__global__ __launch_bounds__(NTH, 1)
void knrm_kernel(const int* __restrict__ qt,
                 const int* __restrict__ dt,
                 const float* __restrict__ emb,
                 const float* __restrict__ fcw,
                 const float* __restrict__ fcb,
                 float* __restrict__ out)
{
    extern __shared__ float sm[];
    float* dR = sm;                      // [DCH][RS] doc tile (row-major)
    float* qR = dR + DCH * RS;           // [BQ][RS]  query tile
    float* rq = qR + BQ * RS;            // [BQ]
    float* wq = rq + BQ;                 // [BQ]
    float* rd = wq + BQ;                 // [DCH]
    float* wd = rd + DCH;                // [DCH]
    float* qk = wd + DCH;                // [BQ][NK]

    const int b    = blockIdx.x;
    const int tid  = threadIdx.x;
    const int lane = tid & 31;
    const int warp = tid >> 5;           // 0..15

    for (int i = tid; i < BQ * NK; i += NTH) qk[i] = 0.0f;

    // ---- load 32 query rows (2 per warp) ----
    #pragma unroll
    for (int r = 0; r < BQ / 16; ++r) {
        const int q   = warp * (BQ / 16) + r;
        const int tok = qt[b * BQ + q];
        float ssq = warp_sum(load_row(emb, tok, qR + q * RS, lane));
        if (lane == 0) {
            rq[q] = 1.0f / (sqrtf(ssq) + 1e-13f);
            wq[q] = (tok > 0) ? 1.0f : 0.0f;
        }
    }

    // compute mapping:
    //   p   = warp*16 + (lane&15) in [0,256): output tile index
    //   eh  = lane>>4             : E-half (0: e[0,152), 1: e[152,300))
    //   tq  = p&7  -> q rows {tq, tq+8, tq+16, tq+24}
    //   tdg = p>>3 -> d rows {tdg, tdg+32, tdg+64, tdg+96}
    const int p   = (warp << 4) | (lane & 15);
    const int eh  = lane >> 4;
    const int tq  = p & 7;
    const int tdg = p >> 3;

    const unsigned ehOff = (unsigned)eh * (38u * 16u);   // 38 granules
    const unsigned qA = sm_u32(qR) + (unsigned)tq  * (RS * 4) + ehOff;
    const unsigned dA = sm_u32(dR) + (unsigned)tdg * (RS * 4) + ehOff;

    float rqv[4], wqv[4];
    float rdv[2], wdv[2];

    for (int ch = 0; ch < NCHUNK; ++ch) {
        __syncthreads();   // previous chunk readers done

        // ---- load 128 doc rows (8 per warp) ----
        #pragma unroll 2
        for (int r = 0; r < DCH / 16; ++r) {
            const int dloc = warp * (DCH / 16) + r;
            const int tok  = dt[b * BD + ch * DCH + dloc];
            float ssq = warp_sum(load_row(emb, tok, dR + dloc * RS, lane));
            if (lane == 0) {
                rd[dloc] = 1.0f / (sqrtf(ssq) + 1e-13f);
                wd[dloc] = (tok > 0) ? 1.0f : 0.0f;
            }
        }
        __syncthreads();

        if (ch == 0) {
            #pragma unroll
            for (int i = 0; i < 4; ++i) {
                rqv[i] = rq[tq + 8 * i];
                wqv[i] = wq[tq + 8 * i];
            }
        }

        // ---- 4x4 partial GEMM over this E-half, packed f32x2 ----
        ull acc2[4][4];
        #pragma unroll
        for (int i = 0; i < 4; ++i)
            #pragma unroll
            for (int j = 0; j < 4; ++j) acc2[i][j] = 0ull;

        unsigned qa = qA, da = dA;
        #pragma unroll 2
        for (int it = 0; it < IT_COMMON; ++it) {
            ull ql[4][2], dl[4][2];
            #pragma unroll
            for (int i = 0; i < 4; ++i)
                lds_v2u64(ql[i][0], ql[i][1], qa + i * (8 * RS * 4));
            #pragma unroll
            for (int j = 0; j < 4; ++j)
                lds_v2u64(dl[j][0], dl[j][1], da + j * (32 * RS * 4));
            #pragma unroll
            for (int i = 0; i < 4; ++i)
                #pragma unroll
                for (int j = 0; j < 4; ++j) {
                    fma2(acc2[i][j], ql[i][0], dl[j][0]);
                    fma2(acc2[i][j], ql[i][1], dl[j][1]);
                }
            qa += 16; da += 16;
        }
        if (eh == 0) {   // eh0 covers 38 granules (e 0..151), eh1 only 37
            ull ql[4][2], dl[4][2];
            #pragma unroll
            for (int i = 0; i < 4; ++i)
                lds_v2u64(ql[i][0], ql[i][1], qa + i * (8 * RS * 4));
            #pragma unroll
            for (int j = 0; j < 4; ++j)
                lds_v2u64(dl[j][0], dl[j][1], da + j * (32 * RS * 4));
            #pragma unroll
            for (int i = 0; i < 4; ++i)
                #pragma unroll
                for (int j = 0; j < 4; ++j) {
                    fma2(acc2[i][j], ql[i][0], dl[j][0]);
                    fma2(acc2[i][j], ql[i][1], dl[j][1]);
                }
        }

        // ---- combine E-halves across partner lanes (lane ^ 16) ----
        float mfull[4][4];
        #pragma unroll
        for (int i = 0; i < 4; ++i)
            #pragma unroll
            for (int j = 0; j < 4; ++j) {
                float lo, hi;
                asm("mov.b64 {%0, %1}, %2;" : "=f"(lo), "=f"(hi) : "l"(acc2[i][j]));
                float s = lo + hi;
                mfull[i][j] = s + __shfl_xor_sync(0xffffffffu, s, 16);
            }

        // ---- RBF epilogue: this thread handles j in {2*eh, 2*eh+1} ----
        #pragma unroll
        for (int jj = 0; jj < 2; ++jj) {
            const int j = 2 * eh + jj;
            rdv[jj] = rd[tdg + 32 * j];
            wdv[jj] = wd[tdg + 32 * j];
        }

        float kacc[4][NK];
        #pragma unroll
        for (int i = 0; i < 4; ++i)
            #pragma unroll
            for (int k = 0; k < NK; ++k) kacc[i][k] = 0.0f;

        #pragma unroll
        for (int i = 0; i < 4; ++i) {
            #pragma unroll
            for (int jj = 0; jj < 2; ++jj) {
                const int j = 2 * eh + jj;
                const float m = mfull[i][j] * (rqv[i] * rdv[jj]);
                const float w = wqv[i] * wdv[jj];
                #pragma unroll
                for (int k = 0; k < NK; ++k) {
                    const float d0 = m - c_mu[k];
                    kacc[i][k] = fmaf(w, ex2(d0 * d0 * c_cl[k]), kacc[i][k]);
                }
            }
        }

        // ---- per-chunk reduce: lanes {l, l+8, l+16, l+24} share tq ----
        #pragma unroll
        for (int i = 0; i < 4; ++i) {
            #pragma unroll
            for (int k = 0; k < NK; ++k) {
                float v = kacc[i][k];
                v += __shfl_down_sync(0xffffffffu, v, 16);
                v += __shfl_down_sync(0xffffffffu, v, 8);
                if (lane < 8) atomicAdd(&qk[(tq + 8 * i) * NK + k], v);
            }
        }
    }
    __syncthreads();

    // ---- log-pool over Q, FC, write score ----
    if (tid < BQ) {
        float s = 0.0f;
        #pragma unroll
        for (int k = 0; k < NK; ++k)
            s += fcw[k] * 0.01f * logf(fmaxf(qk[tid * NK + k], 1e-10f));
        s = warp_sum(s);
        if (lane == 0) out[b] = s + fcb[0];
    }
}

extern "C" void kernel_launch(void* const* d_in, const int* in_sizes, int n_in,
                              void* d_out, int out_size)
{
    const int*   qt  = (const int*)d_in[0];
    const int*   dt  = (const int*)d_in[1];
    const float* emb = (const float*)d_in[2];
    const float* fcw = (const float*)d_in[3];
    const float* fcb = (const float*)d_in[4];
    float* out = (float*)d_out;

    const int B = in_sizes[0] / BQ;   // 256

    const size_t smem = (size_t)((DCH + BQ) * RS + 2 * BQ + 2 * DCH + BQ * NK)
                        * sizeof(float);   // 194,688 B
    cudaFuncSetAttribute(knrm_kernel,
                         cudaFuncAttributeMaxDynamicSharedMemorySize, (int)smem);
    knrm_kernel<<<B, NTH, smem>>>(qt, dt, emb, fcw, fcb, out);
}

// round 8
// speedup vs baseline: 3.5328x; 2.1209x over previous
#include <cuda_runtime.h>
#include <cuda_fp16.h>

#define BQ     32
#define BD     512
#define EDIM   300
#define NK     11
#define DCH    128
#define NCHUNK (BD / DCH)
#define RSH    312            // halfs per row (624 B = 39 granules, odd -> conflict-free)
#define RSB    (RSH * 2)      // bytes per row
#define KSTEPS 19             // K padded 300 -> 304 = 19*16
#define NTH    256

__device__ __constant__ float c_mu10[10] =
    {0.9f, 0.7f, 0.5f, 0.3f, 0.1f, -0.1f, -0.3f, -0.5f, -0.7f, -0.9f};
// c_tc10[k] = -50*log2(e)*mu^2
__device__ __constant__ float c_tc10[10] =
    {-58.4291492f, -35.3460285f, -18.0336880f, -6.49212768f, -0.721347520f,
     -0.721347520f, -6.49212768f, -18.0336880f, -35.3460285f, -58.4291492f};

#define K50L2E  72.1347520f   //  50*log2(e)
#define K100L2E 144.269504f   // 100*log2(e)

__device__ __forceinline__ float warp_sum(float v) {
    v += __shfl_xor_sync(0xffffffffu, v, 16);
    v += __shfl_xor_sync(0xffffffffu, v, 8);
    v += __shfl_xor_sync(0xffffffffu, v, 4);
    v += __shfl_xor_sync(0xffffffffu, v, 2);
    v += __shfl_xor_sync(0xffffffffu, v, 1);
    return v;
}

__device__ __forceinline__ unsigned sm_u32(const void* p) {
    unsigned r;
    asm("{ .reg .u64 t; cvta.to.shared.u64 t, %1; cvt.u32.u64 %0, t; }"
        : "=r"(r) : "l"(p));
    return r;
}

__device__ __forceinline__ float ex2(float x) {
    float r;
    asm("ex2.approx.f32 %0, %1;" : "=f"(r) : "f"(x));
    return r;
}

__device__ __forceinline__ void ldmx4(unsigned a, unsigned& r0, unsigned& r1,
                                      unsigned& r2, unsigned& r3) {
    asm volatile("ldmatrix.sync.aligned.m8n8.x4.shared.b16 {%0,%1,%2,%3}, [%4];"
                 : "=r"(r0), "=r"(r1), "=r"(r2), "=r"(r3) : "r"(a));
}

__device__ __forceinline__ void ldmx2(unsigned a, unsigned& r0, unsigned& r1) {
    asm volatile("ldmatrix.sync.aligned.m8n8.x2.shared.b16 {%0,%1}, [%2];"
                 : "=r"(r0), "=r"(r1) : "r"(a));
}

__device__ __forceinline__ void mma16816(float* C, unsigned a0, unsigned a1,
                                         unsigned a2, unsigned a3,
                                         unsigned b0, unsigned b1) {
    asm volatile("mma.sync.aligned.m16n8k16.row.col.f32.f16.f16.f32 "
                 "{%0,%1,%2,%3},{%4,%5,%6,%7},{%8,%9},{%0,%1,%2,%3};"
                 : "+f"(C[0]), "+f"(C[1]), "+f"(C[2]), "+f"(C[3])
                 : "r"(a0), "r"(a1), "r"(a2), "r"(a3), "r"(b0), "r"(b1));
}

// Load one embedding row (300 fp32) -> fp16 smem row (coalesced), return partial ssq (fp32)
__device__ __forceinline__ float load_row_h(const float* __restrict__ emb, int tok,
                                            unsigned* dstRow, int lane) {
    const float4* src = reinterpret_cast<const float4*>(emb) + (size_t)tok * (EDIM / 4);
    uint2* d8 = reinterpret_cast<uint2*>(dstRow);
    float ssq = 0.0f;
    float4 v;
    __half2 h0, h1;
    uint2 pk;

    v = src[lane];
    ssq += v.x*v.x + v.y*v.y + v.z*v.z + v.w*v.w;
    h0 = __floats2half2_rn(v.x, v.y); h1 = __floats2half2_rn(v.z, v.w);
    pk.x = *reinterpret_cast<unsigned*>(&h0); pk.y = *reinterpret_cast<unsigned*>(&h1);
    d8[lane] = pk;

    v = src[lane + 32];
    ssq += v.x*v.x + v.y*v.y + v.z*v.z + v.w*v.w;
    h0 = __floats2half2_rn(v.x, v.y); h1 = __floats2half2_rn(v.z, v.w);
    pk.x = *reinterpret_cast<unsigned*>(&h0); pk.y = *reinterpret_cast<unsigned*>(&h1);
    d8[lane + 32] = pk;

    if (lane < 11) {   // 75 float4 per row = 32 + 32 + 11
        v = src[lane + 64];
        ssq += v.x*v.x + v.y*v.y + v.z*v.z + v.w*v.w;
        h0 = __floats2half2_rn(v.x, v.y); h1 = __floats2half2_rn(v.z, v.w);
        pk.x = *reinterpret_cast<unsigned*>(&h0); pk.y = *reinterpret_cast<unsigned*>(&h1);
        d8[lane + 64] = pk;
    }
    return ssq;
}

// RBF accumulate for one (q,d) pair; kernel 0 handled as exact token match count.
__device__ __forceinline__ void rbf_acc(float c, float rqv, int tq, float rdv, int td,
                                        float* kacc) {
    const bool ok = (tq > 0) && (td > 0);
    if (ok && (tq == td)) kacc[0] += 1.0f;
    const float m  = c * (rqv * rdv);
    const float A2 = fmaf(-K50L2E * m, m, ok ? 0.0f : -12000.0f);
    const float Bm = K100L2E * m;
    #pragma unroll
    for (int k = 0; k < 10; ++k) {
        const float t = fmaf(Bm, c_mu10[k], c_tc10[k]);
        kacc[k + 1] += ex2(A2 + t);
    }
}

__global__ __launch_bounds__(NTH, 2)
void knrm_kernel(const int* __restrict__ qt,
                 const int* __restrict__ dt,
                 const float* __restrict__ emb,
                 const float* __restrict__ fcw,
                 const float* __restrict__ fcb,
                 float* __restrict__ out)
{
    extern __shared__ __align__(16) unsigned char smraw[];
    __half* dH  = reinterpret_cast<__half*>(smraw);        // [DCH][RSH]
    __half* qH  = dH + DCH * RSH;                          // [BQ][RSH]
    float*  rq  = reinterpret_cast<float*>(qH + BQ * RSH); // [BQ]
    float*  rd  = rq + BQ;                                 // [DCH]
    int*    qtok = reinterpret_cast<int*>(rd + DCH);       // [BQ]
    int*    dtok = qtok + BQ;                              // [DCH]
    float*  qk  = reinterpret_cast<float*>(dtok + DCH);    // [BQ][NK]

    const int b    = blockIdx.x;
    const int tid  = threadIdx.x;
    const int lane = tid & 31;
    const int warp = tid >> 5;        // 0..7

    for (int i = tid; i < BQ * NK; i += NTH) qk[i] = 0.0f;

    // zero K-pad region (halfs 300..311 = u32 150..155) for all 160 rows; loads never touch it
    for (int i = tid; i < (DCH + BQ) * 3; i += NTH) {
        const int row = i / 3, j = i - row * 3;
        unsigned* base = (row < DCH) ? reinterpret_cast<unsigned*>(dH)
                                     : reinterpret_cast<unsigned*>(qH);
        const int r2 = (row < DCH) ? row : row - DCH;
        base[r2 * (RSH / 2) + 150 + j] = 0u;
    }

    // ---- load 32 query rows (4 per warp), fp16 tiles + fp32 norms + tokens ----
    #pragma unroll
    for (int r = 0; r < BQ / 8; ++r) {
        const int q   = warp * (BQ / 8) + r;
        const int tok = qt[b * BQ + q];
        float ssq = warp_sum(load_row_h(emb, tok,
                        reinterpret_cast<unsigned*>(qH) + q * (RSH / 2), lane));
        if (lane == 0) {
            rq[q] = 1.0f / (sqrtf(ssq) + 1e-13f);
            qtok[q] = tok;
        }
    }

    // warp mapping: mt in {0,1} (16 q-rows), nq in [0,4) (32 docs = 4 n8-tiles)
    const int mt = warp & 1;
    const int nq = warp >> 1;

    const unsigned qBase = sm_u32(qH);
    const unsigned dBase = sm_u32(dH);
    // A (ldmatrix.x4): lane -> row (lane%16), k-offset (lane/16)*8 halfs
    const unsigned aAddr = qBase + (unsigned)(mt * 16 + (lane & 15)) * RSB
                                 + (unsigned)(lane >> 4) * 16;
    // B (ldmatrix.x2): lanes 0-15: row (bl&7), k-offset (bl>>3)*8 halfs
    const int bl = lane & 15;
    const unsigned bAddr0 = dBase + (unsigned)(nq * 32 + (bl & 7)) * RSB
                                  + (unsigned)(bl >> 3) * 16;

    float kacc[2][NK];
    #pragma unroll
    for (int r = 0; r < 2; ++r)
        #pragma unroll
        for (int k = 0; k < NK; ++k) kacc[r][k] = 0.0f;

    const int gr  = lane >> 2;              // row group 0..7
    const int r0q = mt * 16 + gr;           // q row (lo)
    const int r1q = r0q + 8;                // q row (hi)

    for (int ch = 0; ch < NCHUNK; ++ch) {
        __syncthreads();   // previous chunk readers done

        // ---- load 128 doc rows (16 per warp) ----
        #pragma unroll 2
        for (int r = 0; r < DCH / 8; ++r) {
            const int dloc = warp * (DCH / 8) + r;
            const int tok  = dt[b * BD + ch * DCH + dloc];
            float ssq = warp_sum(load_row_h(emb, tok,
                            reinterpret_cast<unsigned*>(dH) + dloc * (RSH / 2), lane));
            if (lane == 0) {
                rd[dloc] = 1.0f / (sqrtf(ssq) + 1e-13f);
                dtok[dloc] = tok;
            }
        }
        __syncthreads();

        // ---- GEMM: 2 m16 x 4 n8 tiles per warp over K=304 (19 k16 steps) ----
        float C[4][4];
        #pragma unroll
        for (int t = 0; t < 4; ++t)
            #pragma unroll
            for (int i = 0; i < 4; ++i) C[t][i] = 0.0f;

        #pragma unroll 1
        for (int kk = 0; kk < KSTEPS; ++kk) {
            unsigned a0, a1, a2, a3, b0, b1;
            ldmx4(aAddr + kk * 32, a0, a1, a2, a3);
            #pragma unroll
            for (int t = 0; t < 4; ++t) {
                ldmx2(bAddr0 + (unsigned)t * (8 * RSB) + kk * 32, b0, b1);
                mma16816(C[t], a0, a1, a2, a3, b0, b1);
            }
        }

        // ---- epilogue: RBF + exact-match count, accumulated in registers ----
        const float rq0 = rq[r0q];
        const float rq1 = rq[r1q];
        const int   tq0 = qtok[r0q];
        const int   tq1 = qtok[r1q];

        #pragma unroll
        for (int t = 0; t < 4; ++t) {
            const int cbase = nq * 32 + t * 8 + 2 * (lane & 3);
            #pragma unroll
            for (int cc = 0; cc < 2; ++cc) {
                const int d  = cbase + cc;
                const float rdv = rd[d];
                const int   td  = dtok[d];
                rbf_acc(C[t][cc],     rq0, tq0, rdv, td, kacc[0]);
                rbf_acc(C[t][cc + 2], rq1, tq1, rdv, td, kacc[1]);
            }
        }
    }

    // ---- reduce kacc across the 4 lanes sharing a row group, then smem atomics ----
    #pragma unroll
    for (int r = 0; r < 2; ++r) {
        const int qrow = mt * 16 + gr + 8 * r;
        #pragma unroll
        for (int k = 0; k < NK; ++k) {
            float v = kacc[r][k];
            v += __shfl_xor_sync(0xffffffffu, v, 1);
            v += __shfl_xor_sync(0xffffffffu, v, 2);
            if ((lane & 3) == 0) atomicAdd(&qk[qrow * NK + k], v);
        }
    }
    __syncthreads();

    // ---- log-pool over Q, FC, write score ----
    if (tid < BQ) {
        float s = 0.0f;
        #pragma unroll
        for (int k = 0; k < NK; ++k)
            s += fcw[k] * 0.01f * logf(fmaxf(qk[tid * NK + k], 1e-10f));
        s = warp_sum(s);
        if (lane == 0) out[b] = s + fcb[0];
    }
}

extern "C" void kernel_launch(void* const* d_in, const int* in_sizes, int n_in,
                              void* d_out, int out_size)
{
    const int*   qt  = (const int*)d_in[0];
    const int*   dt  = (const int*)d_in[1];
    const float* emb = (const float*)d_in[2];
    const float* fcw = (const float*)d_in[3];
    const float* fcb = (const float*)d_in[4];
    float* out = (float*)d_out;

    const int B = in_sizes[0] / BQ;   // 256

    const size_t smem = (size_t)(DCH + BQ) * RSH * sizeof(__half)
                      + (size_t)(BQ + DCH) * sizeof(float)      // rq, rd
                      + (size_t)(BQ + DCH) * sizeof(int)        // qtok, dtok
                      + (size_t)(BQ * NK) * sizeof(float);      // qk  => 102,528 B
    cudaFuncSetAttribute(knrm_kernel,
                         cudaFuncAttributeMaxDynamicSharedMemorySize, (int)smem);
    knrm_kernel<<<B, NTH, smem>>>(qt, dt, emb, fcw, fcb, out);
}